// round 1
// baseline (speedup 1.0000x reference)
#include <cuda_runtime.h>

#define B_  256
#define P_  196
#define E_  2048
#define A_  512
#define M_  (B_*P_)   // 50176 = 392*128

// scratch (no allocs allowed)
__device__ float g_dec_att[B_*A_];     // dec@W_dec + b_dec + b_enc  [256,512]
__device__ float g_partial[M_*4];      // per-128-col-chunk score partials

// ---------------------------------------------------------------------------
// Kernel 0: dec_att[b][a] = decoder_hidden[b]·W_dec[:,a] + b_dec[a] + b_enc[a]
// grid 32 CTAs x 512 thr, each CTA handles 8 batches, 1 column/thread.
// ---------------------------------------------------------------------------
__global__ void dec_att_kernel(const float* __restrict__ dec_h,
                               const float* __restrict__ W_dec,
                               const float* __restrict__ b_dec,
                               const float* __restrict__ b_enc) {
    __shared__ float s_h[8][512];
    int b0  = blockIdx.x * 8;
    int tid = threadIdx.x;
    for (int i = tid; i < 8 * 512; i += 512) {
        int bb = i >> 9, d = i & 511;
        s_h[bb][d] = dec_h[(b0 + bb) * 512 + d];
    }
    __syncthreads();
    int a = tid;
    float acc[8];
#pragma unroll
    for (int bb = 0; bb < 8; bb++) acc[bb] = 0.f;
    for (int d = 0; d < 512; d++) {
        float w = W_dec[d * A_ + a];
#pragma unroll
        for (int bb = 0; bb < 8; bb++) acc[bb] = fmaf(s_h[bb][d], w, acc[bb]);
    }
    float bias = b_dec[a] + b_enc[a];
#pragma unroll
    for (int bb = 0; bb < 8; bb++) g_dec_att[(b0 + bb) * A_ + a] = acc[bb] + bias;
}

// ---------------------------------------------------------------------------
// Kernel 1: fused scores GEMM.
// C[M,512] = enc[M,2048] @ W_enc[2048,512]; epilogue computes per-row
// partial = sum_col relu(C + dec_att[b,col]) * W_att[col] over this 128-col
// chunk, written to g_partial[row][nTile]. Never materializes encoder_att.
// BM=BN=128, BK=16, 256 threads, 8x8 per thread (split 4+4 to avoid bank
// conflicts on frag loads).
// ---------------------------------------------------------------------------
__global__ __launch_bounds__(256, 2)
void scores_kernel(const float* __restrict__ enc,
                   const float* __restrict__ W_enc,
                   const float* __restrict__ W_att) {
    const int BM = 128, BN = 128, BK = 16;
    __shared__ float As[BK][BM + 4];
    __shared__ float Bs[BK][BN];
    __shared__ float red[BM][17];

    int mTile = blockIdx.y, nTile = blockIdx.x;
    int tid = threadIdx.x;
    int tx = tid & 15, ty = tid >> 4;

    const float* Abase = enc + (size_t)mTile * BM * E_;
    const float* Bbase = W_enc + nTile * BN;

    float acc[8][8];
#pragma unroll
    for (int i = 0; i < 8; i++)
#pragma unroll
        for (int j = 0; j < 8; j++) acc[i][j] = 0.f;

    for (int kt = 0; kt < E_ / BK; kt++) {
        // A tile: 128 rows x 16 cols (transposed into As). 512 float4 loads.
#pragma unroll
        for (int s = 0; s < 2; s++) {
            int l   = tid + s * 256;
            int row = l >> 2;
            int c4  = l & 3;
            float4 v = *reinterpret_cast<const float4*>(
                Abase + (size_t)row * E_ + kt * BK + c4 * 4);
            As[c4 * 4 + 0][row] = v.x;
            As[c4 * 4 + 1][row] = v.y;
            As[c4 * 4 + 2][row] = v.z;
            As[c4 * 4 + 3][row] = v.w;
        }
        // B tile: 16 rows x 128 cols, direct.
#pragma unroll
        for (int s = 0; s < 2; s++) {
            int l   = tid + s * 256;
            int row = l >> 5;
            int c4  = l & 31;
            float4 v = *reinterpret_cast<const float4*>(
                Bbase + (size_t)(kt * BK + row) * A_ + c4 * 4);
            *reinterpret_cast<float4*>(&Bs[row][c4 * 4]) = v;
        }
        __syncthreads();
#pragma unroll
        for (int kk = 0; kk < BK; kk++) {
            float4 av0 = *reinterpret_cast<const float4*>(&As[kk][ty * 4]);
            float4 av1 = *reinterpret_cast<const float4*>(&As[kk][64 + ty * 4]);
            float4 bv0 = *reinterpret_cast<const float4*>(&Bs[kk][tx * 4]);
            float4 bv1 = *reinterpret_cast<const float4*>(&Bs[kk][64 + tx * 4]);
            float a[8] = {av0.x, av0.y, av0.z, av0.w, av1.x, av1.y, av1.z, av1.w};
            float b[8] = {bv0.x, bv0.y, bv0.z, bv0.w, bv1.x, bv1.y, bv1.z, bv1.w};
#pragma unroll
            for (int i = 0; i < 8; i++)
#pragma unroll
                for (int j = 0; j < 8; j++)
                    acc[i][j] = fmaf(a[i], b[j], acc[i][j]);
        }
        __syncthreads();
    }

    // Fused epilogue: relu(C + dec_att) · W_att, partial per row over 128 cols
    int row_base = mTile * BM;
    int col_base = nTile * BN;
    float wv[8];
    int colg[8];
#pragma unroll
    for (int j = 0; j < 8; j++) {
        colg[j] = col_base + ((j < 4) ? (tx * 4 + j) : (64 + tx * 4 + j - 4));
        wv[j]   = W_att[colg[j]];   // W_att shape (512,1) -> stride 1
    }
#pragma unroll
    for (int i = 0; i < 8; i++) {
        int m_in = (i < 4) ? (ty * 4 + i) : (64 + ty * 4 + i - 4);
        int grow = row_base + m_in;
        int b    = grow / P_;
        const float* drow = &g_dec_att[b * A_];
        float s = 0.f;
#pragma unroll
        for (int j = 0; j < 8; j++) {
            float v = acc[i][j] + drow[colg[j]];
            v = fmaxf(v, 0.f);
            s = fmaf(v, wv[j], s);
        }
        red[m_in][tx] = s;
    }
    __syncthreads();
    if (tid < BM) {
        float s = 0.f;
#pragma unroll
        for (int t = 0; t < 16; t++) s += red[tid][t];
        g_partial[(size_t)(row_base + tid) * 4 + nTile] = s;
    }
}

// ---------------------------------------------------------------------------
// Kernel 2: softmax over P=196 per batch. grid 256 x 256 thr.
// ---------------------------------------------------------------------------
__global__ void softmax_kernel(const float* __restrict__ b_att,
                               float* __restrict__ alpha_out) {
    __shared__ float s_red[256];
    int b = blockIdx.x, tid = threadIdx.x;
    float sc = 0.f;
    float v  = -1e30f;
    if (tid < P_) {
        const float* p = &g_partial[(size_t)(b * P_ + tid) * 4];
        sc = p[0] + p[1] + p[2] + p[3] + b_att[0];
        v  = sc;
    }
    s_red[tid] = v;
    __syncthreads();
    for (int o = 128; o > 0; o >>= 1) {
        if (tid < o) s_red[tid] = fmaxf(s_red[tid], s_red[tid + o]);
        __syncthreads();
    }
    float mx = s_red[0];
    __syncthreads();
    float e = (tid < P_) ? __expf(sc - mx) : 0.f;
    s_red[tid] = e;
    __syncthreads();
    for (int o = 128; o > 0; o >>= 1) {
        if (tid < o) s_red[tid] += s_red[tid + o];
        __syncthreads();
    }
    float inv = 1.f / s_red[0];
    if (tid < P_) alpha_out[b * P_ + tid] = e * inv;
}

// ---------------------------------------------------------------------------
// Kernel 3: context[b,e] = sum_p enc[b,p,e] * alpha[b,p].  Memory-bound pass.
// grid (8 e-chunks, 256 b), 256 thr, 1 e-value/thread.
// ---------------------------------------------------------------------------
__global__ void context_kernel(const float* __restrict__ enc,
                               const float* __restrict__ alpha,
                               float* __restrict__ ctx) {
    __shared__ float s_a[P_];
    int b = blockIdx.y;
    int e = blockIdx.x * 256 + threadIdx.x;
    if (threadIdx.x < P_) s_a[threadIdx.x] = alpha[b * P_ + threadIdx.x];
    __syncthreads();
    const float* base = enc + (size_t)b * P_ * E_ + e;
    float acc = 0.f;
#pragma unroll 4
    for (int p = 0; p < P_; p++) acc = fmaf(base[(size_t)p * E_], s_a[p], acc);
    ctx[b * E_ + e] = acc;
}

// ---------------------------------------------------------------------------
extern "C" void kernel_launch(void* const* d_in, const int* in_sizes, int n_in,
                              void* d_out, int out_size) {
    const float* enc   = (const float*)d_in[0];
    const float* dech  = (const float*)d_in[1];
    const float* W_enc = (const float*)d_in[2];
    const float* b_enc = (const float*)d_in[3];
    const float* W_dec = (const float*)d_in[4];
    const float* b_dec = (const float*)d_in[5];
    const float* W_att = (const float*)d_in[6];
    const float* b_att = (const float*)d_in[7];

    float* ctx   = (float*)d_out;            // [256, 2048]
    float* alpha = (float*)d_out + B_ * E_;  // [256, 196]

    dec_att_kernel<<<32, 512>>>(dech, W_dec, b_dec, b_enc);
    scores_kernel<<<dim3(4, 392), 256>>>(enc, W_enc, W_att);
    softmax_kernel<<<B_, 256>>>(b_att, alpha);
    context_kernel<<<dim3(8, B_), 256>>>(enc, alpha, ctx);
}

// round 4
// speedup vs baseline: 2.8619x; 2.8619x over previous
#include <cuda_runtime.h>
#include <cstdint>

#define B_  256
#define P_  196
#define E_  2048
#define A_  512
#define M_  (B_*P_)   // 50176 = 392*128
#define BK  32

// ---------------- device scratch (no allocs allowed) ----------------
__device__ float g_dec_att[B_*A_];                 // dec@W_dec + b_dec + b_enc
__device__ __align__(16) float g_Wt[A_*E_];        // W_enc^T, tf32-rounded, [n][k]
__device__ float g_partial[M_*4];                  // per-128-col score partials

// ---------------- helpers ----------------
__device__ __forceinline__ uint32_t smem_u32(const void* p) {
    uint32_t a;
    asm("{ .reg .u64 t; cvta.to.shared.u64 t, %1; cvt.u32.u64 %0, t; }"
        : "=r"(a) : "l"(p));
    return a;
}
__device__ __forceinline__ float to_tf32(float x) {
    float r; asm("cvt.rna.tf32.f32 %0, %1;" : "=f"(r) : "f"(x)); return r;
}
#define CP_ASYNC16(dst_u32, src_ptr) \
    asm volatile("cp.async.cg.shared.global [%0], [%1], 16;" \
                 :: "r"(dst_u32), "l"(src_ptr) : "memory")
#define CP_COMMIT()  asm volatile("cp.async.commit_group;" ::: "memory")
#define CP_WAIT0()   asm volatile("cp.async.wait_group 0;" ::: "memory")

__device__ __forceinline__ void mma_tf32(float* d, const float* a, const float* b) {
    asm volatile(
        "mma.sync.aligned.m16n8k8.row.col.f32.tf32.tf32.f32 "
        "{%0,%1,%2,%3}, {%4,%5,%6,%7}, {%8,%9}, {%0,%1,%2,%3};"
        : "+f"(d[0]), "+f"(d[1]), "+f"(d[2]), "+f"(d[3])
        : "r"(__float_as_uint(a[0])), "r"(__float_as_uint(a[1])),
          "r"(__float_as_uint(a[2])), "r"(__float_as_uint(a[3])),
          "r"(__float_as_uint(b[0])), "r"(__float_as_uint(b[1])));
}

// ---------------------------------------------------------------------------
// W prep: g_Wt[n][k] = tf32_rna(W_enc[k][n])
// ---------------------------------------------------------------------------
__global__ void wt_prep(const float* __restrict__ W_enc) {
    __shared__ float t[32][33];
    int kt = blockIdx.x * 32, nt = blockIdx.y * 32;
    t[threadIdx.y][threadIdx.x] =
        W_enc[(size_t)(kt + threadIdx.y) * A_ + nt + threadIdx.x];
    __syncthreads();
    g_Wt[(size_t)(nt + threadIdx.y) * E_ + kt + threadIdx.x] =
        to_tf32(t[threadIdx.x][threadIdx.y]);
}

// ---------------------------------------------------------------------------
// dec_att[b][a] = dec_h[b]·W_dec[:,a] + b_dec[a] + b_enc[a]   (fp32)
// ---------------------------------------------------------------------------
__global__ void dec_att_kernel(const float* __restrict__ dec_h,
                               const float* __restrict__ W_dec,
                               const float* __restrict__ b_dec,
                               const float* __restrict__ b_enc) {
    __shared__ float s_h[8][512];
    int b0  = blockIdx.x * 8;
    int tid = threadIdx.x;
    for (int i = tid; i < 8 * 512; i += 512)
        s_h[i >> 9][i & 511] = dec_h[(b0 + (i >> 9)) * 512 + (i & 511)];
    __syncthreads();
    int a = tid;
    float acc[8];
#pragma unroll
    for (int bb = 0; bb < 8; bb++) acc[bb] = 0.f;
    for (int d = 0; d < 512; d++) {
        float w = W_dec[d * A_ + a];
#pragma unroll
        for (int bb = 0; bb < 8; bb++) acc[bb] = fmaf(s_h[bb][d], w, acc[bb]);
    }
    float bias = b_dec[a] + b_enc[a];
#pragma unroll
    for (int bb = 0; bb < 8; bb++) g_dec_att[(b0 + bb) * A_ + a] = acc[bb] + bias;
}

// ---------------------------------------------------------------------------
// Fused scores GEMM on the tensor pipe (mma.sync tf32).
// CTA: 128m x 128n x 32k, 8 warps (2m x 4n), warp tile 64x32 = 4x4 m16n8k8.
// Smem rows padded to 44 floats (bank-conflict-free frag loads + 16B stores).
// Epilogue: relu(C + dec_att)·W_att -> g_partial[row][nTile].
// ---------------------------------------------------------------------------
#define SPAD    44
#define TILE_F  (128*SPAD)                 // 5632 floats per matrix tile
#define STAGE_F (2*TILE_F)                 // 11264 (A+B)
#define OFF_DEC (2*STAGE_F)                // float index 22528
#define OFF_WATT (OFF_DEC + 256)
#define OFF_RED  (OFF_WATT + 128)
#define SMEM_FLOATS (OFF_RED + 512)
#define SMEM_BYTES  (SMEM_FLOATS * 4)      // 93,696 B

__global__ __launch_bounds__(256)
void scores_mma(const float* __restrict__ enc, const float* __restrict__ W_att) {
    extern __shared__ float sm[];
    const uint32_t sb = smem_u32(sm);

    const int tid  = threadIdx.x;
    const int lane = tid & 31, wid = tid >> 5;
    const int qr = lane >> 2, qc = lane & 3;
    const int wm = wid >> 2, wn = wid & 3;          // 2 x 4 warp grid
    const int nT = blockIdx.x, mT = blockIdx.y;
    const int mBase = mT * 128, nBase = nT * 128;
    const int b0 = mBase / P_;

    const int rowb = tid >> 3, c4 = tid & 7;        // load mapping

    float* s_dec  = sm + OFF_DEC;
    float* s_watt = sm + OFF_WATT;
    float* s_red  = sm + OFF_RED;

    // ---------------- prologue: stage 0 ----------------
    {   // A: LDG + cvt.rna + STS (layout [m][44])
#pragma unroll
        for (int i = 0; i < 4; i++) {
            int r = rowb + 32 * i;
            float4 v = *(const float4*)(enc + (size_t)(mBase + r) * E_ + c4 * 4);
            float4 t = { to_tf32(v.x), to_tf32(v.y), to_tf32(v.z), to_tf32(v.w) };
            *(float4*)(sm + r * SPAD + c4 * 4) = t;
        }
        // B: cp.async from pre-rounded g_Wt (layout [n][44]); rows nBase+n
#pragma unroll
        for (int i = 0; i < 4; i++) {
            int n = rowb + 32 * i;
            CP_ASYNC16(sb + (uint32_t)(TILE_F * 4 + n * (SPAD * 4) + c4 * 16),
                       g_Wt + (size_t)(nBase + n) * E_ + c4 * 4);
        }
        CP_COMMIT();
    }
    // dec rows (2 batches) + W_att slice for this CTA's 128 cols
    {
        int bb = b0 + (tid >> 7);
        if (bb >= B_) bb = B_ - 1;
        s_dec[tid] = g_dec_att[bb * A_ + nBase + (tid & 127)];
        if (tid < 128) s_watt[tid] = W_att[nBase + tid];
    }
    CP_WAIT0();
    __syncthreads();

    float acc[4][4][4];
#pragma unroll
    for (int mi = 0; mi < 4; mi++)
#pragma unroll
        for (int ni = 0; ni < 4; ni++)
#pragma unroll
            for (int j = 0; j < 4; j++) acc[mi][ni][j] = 0.f;

    // ---------------- main loop ----------------
    for (int kt = 0; kt < E_ / BK; kt++) {
        float* Ac = sm + (kt & 1) * STAGE_F;
        float* Bc = Ac + TILE_F;
        float4 areg[4];
        const int k0n = (kt + 1) * BK;
        const bool more = (kt < E_ / BK - 1);

        if (more) {
#pragma unroll
            for (int i = 0; i < 4; i++)
                areg[i] = *(const float4*)(enc + (size_t)(mBase + rowb + 32 * i) * E_
                                           + k0n + c4 * 4);
            uint32_t bdst = sb + ((kt & 1) ^ 1) * (STAGE_F * 4) + TILE_F * 4;
#pragma unroll
            for (int i = 0; i < 4; i++) {
                int n = rowb + 32 * i;
                CP_ASYNC16(bdst + (uint32_t)(n * (SPAD * 4) + c4 * 16),
                           g_Wt + (size_t)(nBase + n) * E_ + k0n + c4 * 4);
            }
            CP_COMMIT();
        }

#pragma unroll
        for (int ks = 0; ks < 4; ks++) {
            float a[4][4], b[4][2];
#pragma unroll
            for (int mi = 0; mi < 4; mi++) {
                const float* ap = Ac + (wm * 64 + mi * 16 + qr) * SPAD + ks * 8 + qc;
                a[mi][0] = ap[0];
                a[mi][1] = ap[8 * SPAD];
                a[mi][2] = ap[4];
                a[mi][3] = ap[8 * SPAD + 4];
            }
#pragma unroll
            for (int ni = 0; ni < 4; ni++) {
                const float* bp = Bc + (wn * 32 + ni * 8 + qr) * SPAD + ks * 8 + qc;
                b[ni][0] = bp[0];
                b[ni][1] = bp[4];
            }
#pragma unroll
            for (int mi = 0; mi < 4; mi++)
#pragma unroll
                for (int ni = 0; ni < 4; ni++)
                    mma_tf32(acc[mi][ni], a[mi], b[ni]);
        }

        if (more) {
            float* An = sm + ((kt & 1) ^ 1) * STAGE_F;
#pragma unroll
            for (int i = 0; i < 4; i++) {
                float4 t = { to_tf32(areg[i].x), to_tf32(areg[i].y),
                             to_tf32(areg[i].z), to_tf32(areg[i].w) };
                *(float4*)(An + (rowb + 32 * i) * SPAD + c4 * 4) = t;
            }
            CP_WAIT0();
        }
        __syncthreads();
    }

    // ---------------- epilogue: relu(+dec)·W_att, per-row partials ----------------
#pragma unroll
    for (int mi = 0; mi < 4; mi++) {
#pragma unroll
        for (int half = 0; half < 2; half++) {
            int rl = wm * 64 + mi * 16 + qr + half * 8;
            int bloc = (mBase + rl) / P_ - b0;          // 0 or 1
            const float* drow = s_dec + bloc * 128;
            float s = 0.f;
#pragma unroll
            for (int ni = 0; ni < 4; ni++) {
#pragma unroll
                for (int j = 0; j < 2; j++) {
                    int c = wn * 32 + ni * 8 + qc * 2 + j;
                    float v = acc[mi][ni][half * 2 + j] + drow[c];
                    v = fmaxf(v, 0.f);
                    s = fmaf(v, s_watt[c], s);
                }
            }
            s += __shfl_xor_sync(0xffffffffu, s, 1);
            s += __shfl_xor_sync(0xffffffffu, s, 2);
            if (qc == 0) s_red[rl * 4 + wn] = s;
        }
    }
    __syncthreads();
    if (tid < 128) {
        const float* p = s_red + tid * 4;
        g_partial[(size_t)(mBase + tid) * 4 + nT] = p[0] + p[1] + p[2] + p[3];
    }
}

// ---------------------------------------------------------------------------
// softmax over P=196 per batch (sums the 4 col-chunk partials; b_att cancels)
// ---------------------------------------------------------------------------
__global__ void softmax_kernel(float* __restrict__ alpha_out) {
    __shared__ float s_red[256];
    int b = blockIdx.x, tid = threadIdx.x;
    float sc = 0.f;
    float v  = -1e30f;
    if (tid < P_) {
        const float* p = &g_partial[(size_t)(b * P_ + tid) * 4];
        sc = p[0] + p[1] + p[2] + p[3];
        v  = sc;
    }
    s_red[tid] = v;
    __syncthreads();
    for (int o = 128; o > 0; o >>= 1) {
        if (tid < o) s_red[tid] = fmaxf(s_red[tid], s_red[tid + o]);
        __syncthreads();
    }
    float mx = s_red[0];
    __syncthreads();
    float e = (tid < P_) ? __expf(sc - mx) : 0.f;
    s_red[tid] = e;
    __syncthreads();
    for (int o = 128; o > 0; o >>= 1) {
        if (tid < o) s_red[tid] += s_red[tid + o];
        __syncthreads();
    }
    float inv = 1.f / s_red[0];
    if (tid < P_) alpha_out[b * P_ + tid] = e * inv;
}

// ---------------------------------------------------------------------------
// context[b,:] = alpha[b,:] @ enc[b]   (float4 + 2-way ILP)
// ---------------------------------------------------------------------------
__global__ void context_kernel(const float* __restrict__ enc,
                               const float* __restrict__ alpha,
                               float* __restrict__ ctx) {
    __shared__ float s_a[P_];
    int b = blockIdx.y;
    for (int i = threadIdx.x; i < P_; i += 128) s_a[i] = alpha[b * P_ + i];
    __syncthreads();
    int e4 = blockIdx.x * 128 + threadIdx.x;   // 0..511
    const float4* base = (const float4*)(enc + (size_t)b * P_ * E_) + e4;
    float4 a0 = {0, 0, 0, 0}, a1 = {0, 0, 0, 0};
#pragma unroll 2
    for (int p = 0; p < P_; p += 2) {
        float4 v0 = base[(size_t)p * (E_ / 4)];
        float4 v1 = base[(size_t)(p + 1) * (E_ / 4)];
        float w0 = s_a[p], w1 = s_a[p + 1];
        a0.x = fmaf(w0, v0.x, a0.x); a0.y = fmaf(w0, v0.y, a0.y);
        a0.z = fmaf(w0, v0.z, a0.z); a0.w = fmaf(w0, v0.w, a0.w);
        a1.x = fmaf(w1, v1.x, a1.x); a1.y = fmaf(w1, v1.y, a1.y);
        a1.z = fmaf(w1, v1.z, a1.z); a1.w = fmaf(w1, v1.w, a1.w);
    }
    float4 r = {a0.x + a1.x, a0.y + a1.y, a0.z + a1.z, a0.w + a1.w};
    ((float4*)(ctx + (size_t)b * E_))[e4] = r;
}

// ---------------------------------------------------------------------------
extern "C" void kernel_launch(void* const* d_in, const int* in_sizes, int n_in,
                              void* d_out, int out_size) {
    const float* enc   = (const float*)d_in[0];
    const float* dech  = (const float*)d_in[1];
    const float* W_enc = (const float*)d_in[2];
    const float* b_enc = (const float*)d_in[3];
    const float* W_dec = (const float*)d_in[4];
    const float* b_dec = (const float*)d_in[5];
    const float* W_att = (const float*)d_in[6];
    // d_in[7] = b_att: constant shift, cancels in softmax.

    float* ctx   = (float*)d_out;            // [256, 2048]
    float* alpha = (float*)d_out + B_ * E_;  // [256, 196]

    cudaFuncSetAttribute(scores_mma, cudaFuncAttributeMaxDynamicSharedMemorySize,
                         SMEM_BYTES);

    wt_prep<<<dim3(E_ / 32, A_ / 32), dim3(32, 32)>>>(W_enc);
    dec_att_kernel<<<32, 512>>>(dech, W_dec, b_dec, b_enc);
    scores_mma<<<dim3(4, 392), 256, SMEM_BYTES>>>(enc, W_att);
    softmax_kernel<<<B_, 256>>>(alpha);
    context_kernel<<<dim3(4, B_), 128>>>(enc, alpha, ctx);
}

// round 5
// speedup vs baseline: 2.8980x; 1.0126x over previous
#include <cuda_runtime.h>
#include <cstdint>

#define B_  256
#define P_  196
#define E_  2048
#define A_  512
#define M_  (B_*P_)   // 50176 = 392*128
#define BK  32

// ---------------- device scratch (no allocs allowed) ----------------
__device__ float g_dec_att[B_*A_];                 // dec@W_dec + b_dec + b_enc
__device__ __align__(16) float g_Wt[A_*E_];        // W_enc^T, tf32-rounded, [n][k]
__device__ float g_partial[M_*4];                  // per-128-col score partials

// ---------------- helpers ----------------
__device__ __forceinline__ uint32_t smem_u32(const void* p) {
    uint32_t a;
    asm("{ .reg .u64 t; cvta.to.shared.u64 t, %1; cvt.u32.u64 %0, t; }"
        : "=r"(a) : "l"(p));
    return a;
}
__device__ __forceinline__ float to_tf32(float x) {
    float r; asm("cvt.rna.tf32.f32 %0, %1;" : "=f"(r) : "f"(x)); return r;
}
#define CP_ASYNC16(dst_u32, src_ptr) \
    asm volatile("cp.async.cg.shared.global [%0], [%1], 16;" \
                 :: "r"(dst_u32), "l"(src_ptr) : "memory")
#define CP_COMMIT()  asm volatile("cp.async.commit_group;" ::: "memory")
#define CP_WAIT0()   asm volatile("cp.async.wait_group 0;" ::: "memory")

__device__ __forceinline__ void mma_tf32(float* d, const float* a, const float* b) {
    asm volatile(
        "mma.sync.aligned.m16n8k8.row.col.f32.tf32.tf32.f32 "
        "{%0,%1,%2,%3}, {%4,%5,%6,%7}, {%8,%9}, {%0,%1,%2,%3};"
        : "+f"(d[0]), "+f"(d[1]), "+f"(d[2]), "+f"(d[3])
        : "r"(__float_as_uint(a[0])), "r"(__float_as_uint(a[1])),
          "r"(__float_as_uint(a[2])), "r"(__float_as_uint(a[3])),
          "r"(__float_as_uint(b[0])), "r"(__float_as_uint(b[1])));
}

// ---------------------------------------------------------------------------
// W prep: g_Wt[n][k] = tf32_rna(W_enc[k][n])
// ---------------------------------------------------------------------------
__global__ void wt_prep(const float* __restrict__ W_enc) {
    __shared__ float t[32][33];
    int kt = blockIdx.x * 32, nt = blockIdx.y * 32;
    t[threadIdx.y][threadIdx.x] =
        W_enc[(size_t)(kt + threadIdx.y) * A_ + nt + threadIdx.x];
    __syncthreads();
    g_Wt[(size_t)(nt + threadIdx.y) * E_ + kt + threadIdx.x] =
        to_tf32(t[threadIdx.x][threadIdx.y]);
}

// ---------------------------------------------------------------------------
// dec_att[b][a] = dec_h[b]·W_dec[:,a] + b_dec[a] + b_enc[a]   (fp32)
// ---------------------------------------------------------------------------
__global__ void dec_att_kernel(const float* __restrict__ dec_h,
                               const float* __restrict__ W_dec,
                               const float* __restrict__ b_dec,
                               const float* __restrict__ b_enc) {
    __shared__ float s_h[8][512];
    int b0  = blockIdx.x * 8;
    int tid = threadIdx.x;
    for (int i = tid; i < 8 * 512; i += 512)
        s_h[i >> 9][i & 511] = dec_h[(b0 + (i >> 9)) * 512 + (i & 511)];
    __syncthreads();
    int a = tid;
    float acc[8];
#pragma unroll
    for (int bb = 0; bb < 8; bb++) acc[bb] = 0.f;
    for (int d = 0; d < 512; d++) {
        float w = W_dec[d * A_ + a];
#pragma unroll
        for (int bb = 0; bb < 8; bb++) acc[bb] = fmaf(s_h[bb][d], w, acc[bb]);
    }
    float bias = b_dec[a] + b_enc[a];
#pragma unroll
    for (int bb = 0; bb < 8; bb++) g_dec_att[(b0 + bb) * A_ + a] = acc[bb] + bias;
}

// ---------------------------------------------------------------------------
// Fused scores GEMM on the tensor pipe (mma.sync tf32).
// CTA: 128m x 128n x 32k, 8 warps (2m x 4n), warp tile 64x32 = 4x4 m16n8k8.
// SPAD=36 (conflict-free frag loads, 16B-aligned stores); 77.3 KB smem and
// launch_bounds(256,2) -> 2 CTAs/SM for latency hiding.
// Epilogue: relu(C + dec_att)·W_att -> g_partial[row][nTile].
// ---------------------------------------------------------------------------
#define SPAD    36
#define TILE_F  (128*SPAD)                 // 4608 floats per matrix tile
#define STAGE_F (2*TILE_F)                 // 9216 (A+B)
#define OFF_DEC (2*STAGE_F)                // float index 18432
#define OFF_WATT (OFF_DEC + 256)
#define OFF_RED  (OFF_WATT + 128)
#define SMEM_FLOATS (OFF_RED + 512)
#define SMEM_BYTES  (SMEM_FLOATS * 4)      // 77,312 B

__global__ __launch_bounds__(256, 2)
void scores_mma(const float* __restrict__ enc, const float* __restrict__ W_att) {
    extern __shared__ float sm[];
    const uint32_t sb = smem_u32(sm);

    const int tid  = threadIdx.x;
    const int lane = tid & 31, wid = tid >> 5;
    const int qr = lane >> 2, qc = lane & 3;
    const int wm = wid >> 2, wn = wid & 3;          // 2 x 4 warp grid
    const int nT = blockIdx.x, mT = blockIdx.y;
    const int mBase = mT * 128, nBase = nT * 128;
    const int b0 = mBase / P_;

    const int rowb = tid >> 3, c4 = tid & 7;        // load mapping

    float* s_dec  = sm + OFF_DEC;
    float* s_watt = sm + OFF_WATT;
    float* s_red  = sm + OFF_RED;

    // ---------------- prologue: stage 0 ----------------
    {   // A: LDG + cvt.rna + STS (layout [m][36])
#pragma unroll
        for (int i = 0; i < 4; i++) {
            int r = rowb + 32 * i;
            float4 v = *(const float4*)(enc + (size_t)(mBase + r) * E_ + c4 * 4);
            float4 t = { to_tf32(v.x), to_tf32(v.y), to_tf32(v.z), to_tf32(v.w) };
            *(float4*)(sm + r * SPAD + c4 * 4) = t;
        }
        // B: cp.async from pre-rounded g_Wt (layout [n][36]); rows nBase+n
#pragma unroll
        for (int i = 0; i < 4; i++) {
            int n = rowb + 32 * i;
            CP_ASYNC16(sb + (uint32_t)(TILE_F * 4 + n * (SPAD * 4) + c4 * 16),
                       g_Wt + (size_t)(nBase + n) * E_ + c4 * 4);
        }
        CP_COMMIT();
    }
    // dec rows (2 batches) + W_att slice for this CTA's 128 cols
    {
        int bb = b0 + (tid >> 7);
        if (bb >= B_) bb = B_ - 1;
        s_dec[tid] = g_dec_att[bb * A_ + nBase + (tid & 127)];
        if (tid < 128) s_watt[tid] = W_att[nBase + tid];
    }
    CP_WAIT0();
    __syncthreads();

    float acc[4][4][4];
#pragma unroll
    for (int mi = 0; mi < 4; mi++)
#pragma unroll
        for (int ni = 0; ni < 4; ni++)
#pragma unroll
            for (int j = 0; j < 4; j++) acc[mi][ni][j] = 0.f;

    // ---------------- main loop ----------------
    for (int kt = 0; kt < E_ / BK; kt++) {
        float* Ac = sm + (kt & 1) * STAGE_F;
        float* Bc = Ac + TILE_F;
        float4 areg[4];
        const int k0n = (kt + 1) * BK;
        const bool more = (kt < E_ / BK - 1);

        if (more) {
#pragma unroll
            for (int i = 0; i < 4; i++)
                areg[i] = *(const float4*)(enc + (size_t)(mBase + rowb + 32 * i) * E_
                                           + k0n + c4 * 4);
            uint32_t bdst = sb + ((kt & 1) ^ 1) * (STAGE_F * 4) + TILE_F * 4;
#pragma unroll
            for (int i = 0; i < 4; i++) {
                int n = rowb + 32 * i;
                CP_ASYNC16(bdst + (uint32_t)(n * (SPAD * 4) + c4 * 16),
                           g_Wt + (size_t)(nBase + n) * E_ + k0n + c4 * 4);
            }
            CP_COMMIT();
        }

#pragma unroll
        for (int ks = 0; ks < 4; ks++) {
            float a[4][4], b[4][2];
#pragma unroll
            for (int mi = 0; mi < 4; mi++) {
                const float* ap = Ac + (wm * 64 + mi * 16 + qr) * SPAD + ks * 8 + qc;
                a[mi][0] = ap[0];
                a[mi][1] = ap[8 * SPAD];
                a[mi][2] = ap[4];
                a[mi][3] = ap[8 * SPAD + 4];
            }
#pragma unroll
            for (int ni = 0; ni < 4; ni++) {
                const float* bp = Bc + (wn * 32 + ni * 8 + qr) * SPAD + ks * 8 + qc;
                b[ni][0] = bp[0];
                b[ni][1] = bp[4];
            }
#pragma unroll
            for (int mi = 0; mi < 4; mi++)
#pragma unroll
                for (int ni = 0; ni < 4; ni++)
                    mma_tf32(acc[mi][ni], a[mi], b[ni]);
        }

        if (more) {
            float* An = sm + ((kt & 1) ^ 1) * STAGE_F;
#pragma unroll
            for (int i = 0; i < 4; i++) {
                float4 t = { to_tf32(areg[i].x), to_tf32(areg[i].y),
                             to_tf32(areg[i].z), to_tf32(areg[i].w) };
                *(float4*)(An + (rowb + 32 * i) * SPAD + c4 * 4) = t;
            }
            CP_WAIT0();
        }
        __syncthreads();
    }

    // ---------------- epilogue: relu(+dec)·W_att, per-row partials ----------------
#pragma unroll
    for (int mi = 0; mi < 4; mi++) {
#pragma unroll
        for (int half = 0; half < 2; half++) {
            int rl = wm * 64 + mi * 16 + qr + half * 8;
            int bloc = (mBase + rl) / P_ - b0;          // 0 or 1
            const float* drow = s_dec + bloc * 128;
            float s = 0.f;
#pragma unroll
            for (int ni = 0; ni < 4; ni++) {
#pragma unroll
                for (int j = 0; j < 2; j++) {
                    int c = wn * 32 + ni * 8 + qc * 2 + j;
                    float v = acc[mi][ni][half * 2 + j] + drow[c];
                    v = fmaxf(v, 0.f);
                    s = fmaf(v, s_watt[c], s);
                }
            }
            s += __shfl_xor_sync(0xffffffffu, s, 1);
            s += __shfl_xor_sync(0xffffffffu, s, 2);
            if (qc == 0) s_red[rl * 4 + wn] = s;
        }
    }
    __syncthreads();
    if (tid < 128) {
        const float* p = s_red + tid * 4;
        g_partial[(size_t)(mBase + tid) * 4 + nT] = p[0] + p[1] + p[2] + p[3];
    }
}

// ---------------------------------------------------------------------------
// softmax over P=196 per batch (sums the 4 col-chunk partials; b_att cancels)
// ---------------------------------------------------------------------------
__global__ void softmax_kernel(float* __restrict__ alpha_out) {
    __shared__ float s_red[256];
    int b = blockIdx.x, tid = threadIdx.x;
    float sc = 0.f;
    float v  = -1e30f;
    if (tid < P_) {
        const float* p = &g_partial[(size_t)(b * P_ + tid) * 4];
        sc = p[0] + p[1] + p[2] + p[3];
        v  = sc;
    }
    s_red[tid] = v;
    __syncthreads();
    for (int o = 128; o > 0; o >>= 1) {
        if (tid < o) s_red[tid] = fmaxf(s_red[tid], s_red[tid + o]);
        __syncthreads();
    }
    float mx = s_red[0];
    __syncthreads();
    float e = (tid < P_) ? __expf(sc - mx) : 0.f;
    s_red[tid] = e;
    __syncthreads();
    for (int o = 128; o > 0; o >>= 1) {
        if (tid < o) s_red[tid] += s_red[tid + o];
        __syncthreads();
    }
    float inv = 1.f / s_red[0];
    if (tid < P_) alpha_out[b * P_ + tid] = e * inv;
}

// ---------------------------------------------------------------------------
// context[b,:] = alpha[b,:] @ enc[b]   (float4, 4-way ILP; 196 = 49*4)
// ---------------------------------------------------------------------------
__global__ void context_kernel(const float* __restrict__ enc,
                               const float* __restrict__ alpha,
                               float* __restrict__ ctx) {
    __shared__ float s_a[P_];
    int b = blockIdx.y;
    for (int i = threadIdx.x; i < P_; i += 128) s_a[i] = alpha[b * P_ + i];
    __syncthreads();
    int e4 = blockIdx.x * 128 + threadIdx.x;   // 0..511
    const float4* base = (const float4*)(enc + (size_t)b * P_ * E_) + e4;
    float4 a0 = {0, 0, 0, 0}, a1 = {0, 0, 0, 0};
    float4 a2 = {0, 0, 0, 0}, a3 = {0, 0, 0, 0};
    for (int p = 0; p < P_; p += 4) {
        float4 v0 = base[(size_t)p * (E_ / 4)];
        float4 v1 = base[(size_t)(p + 1) * (E_ / 4)];
        float4 v2 = base[(size_t)(p + 2) * (E_ / 4)];
        float4 v3 = base[(size_t)(p + 3) * (E_ / 4)];
        float w0 = s_a[p], w1 = s_a[p + 1], w2 = s_a[p + 2], w3 = s_a[p + 3];
        a0.x = fmaf(w0, v0.x, a0.x); a0.y = fmaf(w0, v0.y, a0.y);
        a0.z = fmaf(w0, v0.z, a0.z); a0.w = fmaf(w0, v0.w, a0.w);
        a1.x = fmaf(w1, v1.x, a1.x); a1.y = fmaf(w1, v1.y, a1.y);
        a1.z = fmaf(w1, v1.z, a1.z); a1.w = fmaf(w1, v1.w, a1.w);
        a2.x = fmaf(w2, v2.x, a2.x); a2.y = fmaf(w2, v2.y, a2.y);
        a2.z = fmaf(w2, v2.z, a2.z); a2.w = fmaf(w2, v2.w, a2.w);
        a3.x = fmaf(w3, v3.x, a3.x); a3.y = fmaf(w3, v3.y, a3.y);
        a3.z = fmaf(w3, v3.z, a3.z); a3.w = fmaf(w3, v3.w, a3.w);
    }
    float4 r = { (a0.x + a1.x) + (a2.x + a3.x),
                 (a0.y + a1.y) + (a2.y + a3.y),
                 (a0.z + a1.z) + (a2.z + a3.z),
                 (a0.w + a1.w) + (a2.w + a3.w) };
    ((float4*)(ctx + (size_t)b * E_))[e4] = r;
}

// ---------------------------------------------------------------------------
extern "C" void kernel_launch(void* const* d_in, const int* in_sizes, int n_in,
                              void* d_out, int out_size) {
    const float* enc   = (const float*)d_in[0];
    const float* dech  = (const float*)d_in[1];
    const float* W_enc = (const float*)d_in[2];
    const float* b_enc = (const float*)d_in[3];
    const float* W_dec = (const float*)d_in[4];
    const float* b_dec = (const float*)d_in[5];
    const float* W_att = (const float*)d_in[6];
    // d_in[7] = b_att: constant shift, cancels in softmax.

    float* ctx   = (float*)d_out;            // [256, 2048]
    float* alpha = (float*)d_out + B_ * E_;  // [256, 196]

    cudaFuncSetAttribute(scores_mma, cudaFuncAttributeMaxDynamicSharedMemorySize,
                         SMEM_BYTES);

    wt_prep<<<dim3(E_ / 32, A_ / 32), dim3(32, 32)>>>(W_enc);
    dec_att_kernel<<<32, 512>>>(dech, W_dec, b_dec, b_enc);
    scores_mma<<<dim3(4, 392), 256, SMEM_BYTES>>>(enc, W_att);
    softmax_kernel<<<B_, 256>>>(alpha);
    context_kernel<<<dim3(4, B_), 128>>>(enc, alpha, ctx);
}